// round 13
// baseline (speedup 1.0000x reference)
#include <cuda_runtime.h>
#include <cuda_fp16.h>
#include <cstdint>

#define N_NODES 50000
#define N_EDGES 500000

// ---------------------------------------------------------------------------
// Transposed f16 weights + precomputed node tables
//   g_W1t[n][k]  n<512, k<384    g_W2t[n][k]  n<128, k<512
//   g_Xs[node][512] = x @ W1[0:128,:]     g_Xt = x @ W1[128:256,:]
// ---------------------------------------------------------------------------
__device__ __half g_W1t[512 * 384];
__device__ __half g_W2t[128 * 512];
__device__ __half g_Xs[(size_t)N_NODES * 512];
__device__ __half g_Xt[(size_t)N_NODES * 512];

__global__ void cvt_weights_kernel(const float* __restrict__ W1,
                                   const float* __restrict__ W2) {
    int idx = blockIdx.x * blockDim.x + threadIdx.x;
    if (idx < 512 * 384) {
        int n = idx / 384, k = idx % 384;
        g_W1t[idx] = __float2half(W1[k * 512 + n]);
    } else if (idx < 512 * 384 + 128 * 512) {
        int j = idx - 512 * 384;
        int n = j / 512, k = j % 512;
        g_W2t[j] = __float2half(W2[k * 128 + n]);
    }
}

// ---------------------------------------------------------------------------
// PTX helpers (baseline features only — plain sm_103 target)
// ---------------------------------------------------------------------------
__device__ __forceinline__ uint32_t s2u(const void* p) {
    uint32_t a;
    asm("{.reg .u64 t; cvta.to.shared.u64 t, %1; cvt.u32.u64 %0, t;}" : "=r"(a) : "l"(p));
    return a;
}
#define CP_ASYNC16(dst, src) \
    asm volatile("cp.async.cg.shared.global [%0], [%1], 16;" :: "r"(dst), "l"(src) : "memory")
#define CP_COMMIT() asm volatile("cp.async.commit_group;" ::: "memory")
#define CP_WAIT(n)  asm volatile("cp.async.wait_group %0;" :: "n"(n) : "memory")

#define LDSM_X4(r0, r1, r2, r3, addr) \
    asm volatile("ldmatrix.sync.aligned.m8n8.x4.shared.b16 {%0,%1,%2,%3}, [%4];" \
                 : "=r"(r0), "=r"(r1), "=r"(r2), "=r"(r3) : "r"(addr))

#define MMA_F16(D, a0, a1, a2, a3, b0, b1) \
    asm volatile("mma.sync.aligned.m16n8k16.row.col.f32.f16.f16.f32 " \
                 "{%0,%1,%2,%3},{%4,%5,%6,%7},{%8,%9},{%0,%1,%2,%3};" \
                 : "+f"((D)[0]), "+f"((D)[1]), "+f"((D)[2]), "+f"((D)[3]) \
                 : "r"(a0), "r"(a1), "r"(a2), "r"(a3), "r"(b0), "r"(b1))

#define STS128(addr, r0, r1, r2, r3) \
    asm volatile("st.shared.v4.b32 [%0], {%1,%2,%3,%4};" \
                 :: "r"(addr), "r"(r0), "r"(r1), "r"(r2), "r"(r3) : "memory")

// A/W1 rows: 128+8 halves = 272 B pitch (conflict-free ldmatrix)
// W2/G/H rows: 64+8 halves = 144 B pitch
static constexpr uint32_t PITCH_K128 = 272;

// ===========================================================================
// Precompute kernel (unchanged): table = x @ W1slice, f16 out.
// ===========================================================================
static constexpr uint32_t P_OFF_A = 0;
static constexpr uint32_t P_OFF_W = 34816;
static constexpr uint32_t P_WBUF  = 17408;
static constexpr uint32_t P_SMEM  = 69632;

__global__ __launch_bounds__(256, 1) void node_pre_kernel(const float* __restrict__ x) {
    extern __shared__ __align__(1024) char smem[];
    const uint32_t sb = s2u(smem);
    const int tid = threadIdx.x, warp = tid >> 5, lane = tid & 31;
    const int n0 = blockIdx.x * 128;
    const int which = blockIdx.y;
    __half* table = which ? g_Xt : g_Xs;

    auto issue_w = [&](int c, int buf) {
        uint32_t dstb = sb + P_OFF_W + (uint32_t)buf * P_WBUF;
        const __half* src = g_W1t + (size_t)(c * 64) * 384 + which * 128;
#pragma unroll
        for (int i = 0; i < 4; i++) {
            int j = tid + i * 256;
            int rr = j >> 4, q = j & 15;
            CP_ASYNC16(dstb + rr * PITCH_K128 + q * 16, src + rr * 384 + q * 8);
        }
    };
    issue_w(0, 0); CP_COMMIT();

    {
        const int r = tid & 127, hb = tid >> 7;
        const int node = min(n0 + r, N_NODES - 1);
        const float* s = x + (size_t)node * 128 + hb * 64;
#pragma unroll
        for (int j = 0; j < 4; j++) {
            const float4* p = (const float4*)(s + j * 16);
            float4 v0 = p[0], v1 = p[1], v2 = p[2], v3 = p[3];
            __half2 h0 = __floats2half2_rn(v0.x, v0.y), h1 = __floats2half2_rn(v0.z, v0.w);
            __half2 h2 = __floats2half2_rn(v1.x, v1.y), h3 = __floats2half2_rn(v1.z, v1.w);
            __half2 h4 = __floats2half2_rn(v2.x, v2.y), h5 = __floats2half2_rn(v2.z, v2.w);
            __half2 h6 = __floats2half2_rn(v3.x, v3.y), h7 = __floats2half2_rn(v3.z, v3.w);
            uint32_t a = sb + P_OFF_A + r * PITCH_K128 + (hb * 64 + j * 16) * 2;
            STS128(a,      *(uint32_t*)&h0, *(uint32_t*)&h1, *(uint32_t*)&h2, *(uint32_t*)&h3);
            STS128(a + 16, *(uint32_t*)&h4, *(uint32_t*)&h5, *(uint32_t*)&h6, *(uint32_t*)&h7);
        }
    }
    __syncthreads();

    const uint32_t aBase = sb + P_OFF_A + (uint32_t)(warp * 16 + (lane & 15)) * PITCH_K128
                         + ((uint32_t)(lane >> 4) << 4);
    const uint32_t wLane = (uint32_t)(lane & 7) * PITCH_K128 + (((uint32_t)(lane >> 3) & 1) << 4)
                         + (uint32_t)(lane >> 4) * (8 * PITCH_K128);
    const int c2i = (lane & 3) * 2;
    const int r0 = warp * 16 + (lane >> 2);
    const int nd0 = n0 + r0, nd1 = nd0 + 8;

    for (int c = 0; c < 8; c++) {
        CP_WAIT(0);
        __syncthreads();
        if (c < 7) { issue_w(c + 1, (c + 1) & 1); CP_COMMIT(); }

        const uint32_t wb = sb + P_OFF_W + (uint32_t)(c & 1) * P_WBUF + wLane;
        float acc[8][4];
#pragma unroll
        for (int t = 0; t < 8; t++)
#pragma unroll
            for (int j = 0; j < 4; j++) acc[t][j] = 0.f;

#pragma unroll
        for (int s = 0; s < 8; s++) {
            uint32_t a0, a1, a2, a3;
            LDSM_X4(a0, a1, a2, a3, aBase + s * 32);
            uint32_t wrow = wb + s * 32;
#pragma unroll
            for (int tp = 0; tp < 4; tp++) {
                uint32_t b0, b1r, b2r, b3;
                LDSM_X4(b0, b1r, b2r, b3, wrow + tp * (16 * PITCH_K128));
                MMA_F16(acc[2 * tp],     a0, a1, a2, a3, b0,  b1r);
                MMA_F16(acc[2 * tp + 1], a0, a1, a2, a3, b2r, b3);
            }
        }
        __syncthreads();

#pragma unroll
        for (int t = 0; t < 8; t++) {
            int n = c * 64 + t * 8 + c2i;
            if (nd0 < N_NODES) {
                __half2 p = __floats2half2_rn(acc[t][0], acc[t][1]);
                *(__half2*)(table + (size_t)nd0 * 512 + n) = p;
            }
            if (nd1 < N_NODES) {
                __half2 p = __floats2half2_rn(acc[t][2], acc[t][3]);
                *(__half2*)(table + (size_t)nd1 * 512 + n) = p;
            }
        }
    }
}

// ===========================================================================
// Edge kernel: 128 edges/CTA, 512 threads (16 warps, 4/SMSP).
// Warp (wm, wn): wm = warp&7 -> edge rows [16wm,16wm+16); wn = warp>>3 -> N half.
// layer1: warp computes 16 edges x 32 cols (wn half of 64); epilogue adds
// gathers+bias, ReLU, stores f16 H to smem staging (double-buffered).
// Pair barrier (wm, wm+8). layer2: warp computes 16 edges x 64 out-cols
// (wn half of 128) reading full H rows via ldmatrix.
// ===========================================================================
#define NTHREADS 512
static constexpr uint32_t OFF_A   = 0;        // 128 x 272 = 34816
static constexpr uint32_t OFF_W1  = 34816;    // 2 x 17408
static constexpr uint32_t W1_BUF  = 17408;
static constexpr uint32_t OFF_W2  = 69632;    // 2 x 18432
static constexpr uint32_t W2_BUF  = 18432;
static constexpr uint32_t OFF_G   = 106496;   // 2 x 36864 ([2][128] x 144B)
static constexpr uint32_t G_BUF   = 36864;
static constexpr uint32_t G_PITCH = 144;
static constexpr uint32_t OFF_H   = 180224;   // 2 x 18432 (128 x 144B)
static constexpr uint32_t H_BUF   = 18432;
static constexpr uint32_t OFF_B1  = 217088;   // 512 f32
static constexpr uint32_t OFF_B2  = 219136;   // 128 f32
static constexpr uint32_t OFF_IDX = 219648;   // 256 int
static constexpr uint32_t SMEM_TOTAL = 220672;

__global__ __launch_bounds__(NTHREADS, 1) void edge_mma_kernel(
    const int*   __restrict__ edge_index,
    const float* __restrict__ edge_attr,
    const float* __restrict__ b1,
    const float* __restrict__ b2,
    float* __restrict__ out)
{
    extern __shared__ __align__(1024) char smem[];
    const uint32_t sb = s2u(smem);
    const int tid = threadIdx.x, warp = tid >> 5, lane = tid & 31;
    const int wm = warp & 7, wn = warp >> 3;
    const int e0 = blockIdx.x * 128;

    float* sB1 = (float*)(smem + OFF_B1);
    float* sB2 = (float*)(smem + OFF_B2);
    int*   sIdx = (int*)(smem + OFF_IDX);   // [0..127]=src, [128..255]=tgt

    auto issue_w1 = [&](int c, int buf) {
        uint32_t dstb = sb + OFF_W1 + (uint32_t)buf * W1_BUF;
        const __half* src = g_W1t + (size_t)(c * 64) * 384 + 256;
#pragma unroll
        for (int i = 0; i < 2; i++) {           // 64 rows x 16 segs = 1024
            int j = tid + i * NTHREADS;
            int rr = j >> 4, q = j & 15;
            CP_ASYNC16(dstb + rr * PITCH_K128 + q * 16, src + rr * 384 + q * 8);
        }
    };
    auto issue_w2 = [&](int c, int buf) {
        uint32_t dstb = sb + OFF_W2 + (uint32_t)buf * W2_BUF;
        const __half* src = g_W2t + c * 64;
#pragma unroll
        for (int i = 0; i < 2; i++) {           // 128 rows x 8 segs = 1024
            int j = tid + i * NTHREADS;
            int rr = j >> 3, q = j & 7;
            CP_ASYNC16(dstb + rr * 144 + q * 16, src + (size_t)rr * 512 + q * 8);
        }
    };
    auto issue_g = [&](int c, int buf) {
        uint32_t dstb = sb + OFF_G + (uint32_t)buf * G_BUF;
        const int cc = c * 64;
#pragma unroll
        for (int i = 0; i < 4; i++) {           // 2 tables x 128 edges x 8 segs = 2048
            int j = tid + i * NTHREADS;
            int seg = j & 7, rest = j >> 3;     // rest 0..255
            int tbl = rest >> 7, edge = rest & 127;
            int row = sIdx[rest];
            const __half* src = (tbl ? g_Xt : g_Xs) + (size_t)row * 512 + cc + seg * 8;
            CP_ASYNC16(dstb + (uint32_t)rest * G_PITCH + seg * 16, src);
        }
    };

    // ---- prologue ----
    if (tid < 256) {
        int half = tid >> 7, r = tid & 127;
        int e = min(e0 + r, N_EDGES - 1);
        sIdx[tid] = edge_index[(size_t)half * N_EDGES + e];
    }
    for (int i = tid; i < 512; i += NTHREADS) sB1[i] = b1[i];
    for (int i = tid; i < 128; i += NTHREADS) sB2[i] = b2[i];

    {   // A build: 4 threads per row, 32 cols each
        const int r = tid >> 2, q = tid & 3;
        const int e = min(e0 + r, N_EDGES - 1);
        const float* s = edge_attr + (size_t)e * 128 + q * 32;
#pragma unroll
        for (int j = 0; j < 2; j++) {
            const float4* p = (const float4*)(s + j * 16);
            float4 v0 = p[0], v1 = p[1], v2 = p[2], v3 = p[3];
            __half2 h0 = __floats2half2_rn(v0.x, v0.y), h1 = __floats2half2_rn(v0.z, v0.w);
            __half2 h2 = __floats2half2_rn(v1.x, v1.y), h3 = __floats2half2_rn(v1.z, v1.w);
            __half2 h4 = __floats2half2_rn(v2.x, v2.y), h5 = __floats2half2_rn(v2.z, v2.w);
            __half2 h6 = __floats2half2_rn(v3.x, v3.y), h7 = __floats2half2_rn(v3.z, v3.w);
            uint32_t a = sb + OFF_A + r * PITCH_K128 + (q * 32 + j * 16) * 2;
            STS128(a,      *(uint32_t*)&h0, *(uint32_t*)&h1, *(uint32_t*)&h2, *(uint32_t*)&h3);
            STS128(a + 16, *(uint32_t*)&h4, *(uint32_t*)&h5, *(uint32_t*)&h6, *(uint32_t*)&h7);
        }
    }
    __syncthreads();        // sIdx visible before gather issue

    issue_g(0, 0); issue_w1(0, 0); issue_w2(0, 0); CP_COMMIT();

    // ---- per-thread fragment addresses ----
    const uint32_t aBase = sb + OFF_A + (uint32_t)(wm * 16 + (lane & 15)) * PITCH_K128
                         + ((uint32_t)(lane >> 4) << 4);
    const uint32_t wLane1 = (uint32_t)(lane & 7) * PITCH_K128 + (((uint32_t)(lane >> 3) & 1) << 4)
                          + (uint32_t)(lane >> 4) * (8 * PITCH_K128)
                          + (uint32_t)wn * (32 * PITCH_K128);
    const uint32_t wLane2 = (uint32_t)(lane & 7) * 144 + (((uint32_t)(lane >> 3) & 1) << 4)
                          + (uint32_t)(lane >> 4) * (8 * 144)
                          + (uint32_t)wn * (64 * 144);
    const uint32_t aBase2rel = (uint32_t)(wm * 16 + (lane & 15)) * 144
                             + ((uint32_t)(lane >> 4) << 4);
    const int c2i = (lane & 3) * 2;
    const int r0 = wm * 16 + (lane >> 2);          // local edge row
    const uint32_t gRd = (uint32_t)r0 * G_PITCH + (uint32_t)wn * 64 + (uint32_t)c2i * 2;
    const uint32_t hWr = (uint32_t)r0 * 144 + (uint32_t)wn * 64 + (uint32_t)c2i * 2;

    float acc2[8][4];
#pragma unroll
    for (int t = 0; t < 8; t++)
#pragma unroll
        for (int j = 0; j < 4; j++) acc2[t][j] = 0.f;

    for (int c = 0; c < 8; c++) {
        CP_WAIT(0);
        __syncthreads();
        if (c < 7) {
            issue_g(c + 1, (c + 1) & 1);
            issue_w1(c + 1, (c + 1) & 1);
            issue_w2(c + 1, (c + 1) & 1);
            CP_COMMIT();
        }

        // ----- layer 1: 16 edges x 32 cols (wn half), K=128 -----
        const uint32_t wb = sb + OFF_W1 + (uint32_t)(c & 1) * W1_BUF + wLane1;
        float acc1[4][4];
#pragma unroll
        for (int t = 0; t < 4; t++)
#pragma unroll
            for (int j = 0; j < 4; j++) acc1[t][j] = 0.f;

#pragma unroll
        for (int s = 0; s < 8; s++) {
            uint32_t a0, a1, a2, a3;
            LDSM_X4(a0, a1, a2, a3, aBase + s * 32);
            uint32_t wrow = wb + s * 32;
#pragma unroll
            for (int tp = 0; tp < 2; tp++) {
                uint32_t b0, b1r, b2r, b3;
                LDSM_X4(b0, b1r, b2r, b3, wrow + tp * (16 * PITCH_K128));
                MMA_F16(acc1[2 * tp],     a0, a1, a2, a3, b0,  b1r);
                MMA_F16(acc1[2 * tp + 1], a0, a1, a2, a3, b2r, b3);
            }
        }

        // ----- epilogue: + Xs + Xt + b1, ReLU, store f16 H to smem -----
        const uint32_t gb = sb + OFF_G + (uint32_t)(c & 1) * G_BUF + gRd;
        const uint32_t hb = sb + OFF_H + (uint32_t)(c & 1) * H_BUF + hWr;
#pragma unroll
        for (int t = 0; t < 4; t++) {
            uint32_t off = (uint32_t)t * 16;
            uint32_t us0, ut0, us1, ut1;
            asm volatile("ld.shared.b32 %0, [%1];" : "=r"(us0) : "r"(gb + off));
            asm volatile("ld.shared.b32 %0, [%1];" : "=r"(ut0) : "r"(gb + 128 * G_PITCH + off));
            asm volatile("ld.shared.b32 %0, [%1];" : "=r"(us1) : "r"(gb + 8 * G_PITCH + off));
            asm volatile("ld.shared.b32 %0, [%1];" : "=r"(ut1) : "r"(gb + 136 * G_PITCH + off));
            int n = c * 64 + wn * 32 + t * 8 + c2i;
            float bb0 = sB1[n], bb1 = sB1[n + 1];
            float2 s0 = __half22float2(*(__half2*)&us0);
            float2 t0 = __half22float2(*(__half2*)&ut0);
            float2 s1 = __half22float2(*(__half2*)&us1);
            float2 t1 = __half22float2(*(__half2*)&ut1);
            float v0 = fmaxf(acc1[t][0] + s0.x + t0.x + bb0, 0.f);
            float v1 = fmaxf(acc1[t][1] + s0.y + t0.y + bb1, 0.f);
            float v2 = fmaxf(acc1[t][2] + s1.x + t1.x + bb0, 0.f);
            float v3 = fmaxf(acc1[t][3] + s1.y + t1.y + bb1, 0.f);
            __half2 p0 = __floats2half2_rn(v0, v1);
            __half2 p1 = __floats2half2_rn(v2, v3);
            asm volatile("st.shared.b32 [%0], %1;" :: "r"(hb + off), "r"(*(uint32_t*)&p0) : "memory");
            asm volatile("st.shared.b32 [%0], %1;" :: "r"(hb + 8 * 144 + off), "r"(*(uint32_t*)&p1) : "memory");
        }

        // pair barrier: warps wm and wm+8 exchange their H halves (64 threads)
        asm volatile("bar.sync %0, 64;" :: "r"(wm + 1) : "memory");

        // ----- layer 2: 16 edges x 64 out-cols (wn half), K=64 -----
        const uint32_t a2b = sb + OFF_H + (uint32_t)(c & 1) * H_BUF + aBase2rel;
        const uint32_t w2b = sb + OFF_W2 + (uint32_t)(c & 1) * W2_BUF + wLane2;
#pragma unroll
        for (int s2 = 0; s2 < 4; s2++) {
            uint32_t ha0, ha1, ha2, ha3;
            LDSM_X4(ha0, ha1, ha2, ha3, a2b + s2 * 32);
            uint32_t wrow = w2b + s2 * 32;
#pragma unroll
            for (int t2p = 0; t2p < 4; t2p++) {
                uint32_t b0, b1r, b2r, b3;
                LDSM_X4(b0, b1r, b2r, b3, wrow + t2p * (16 * 144));
                MMA_F16(acc2[2 * t2p],     ha0, ha1, ha2, ha3, b0,  b1r);
                MMA_F16(acc2[2 * t2p + 1], ha0, ha1, ha2, ha3, b2r, b3);
            }
        }
    }

    // ---- output: + b2 (warp writes its 16 edges x 64-col half) ----
    const int er0 = e0 + r0;
    float* orow0 = out + (size_t)er0 * 128;
#pragma unroll
    for (int t2 = 0; t2 < 8; t2++) {
        int n = wn * 64 + (t2 >> 1) * 16 + (t2 & 1) * 8 + c2i;
        float bb0 = sB2[n], bb1 = sB2[n + 1];
        if (er0 < N_EDGES) {
            float2 v = make_float2(acc2[t2][0] + bb0, acc2[t2][1] + bb1);
            *(float2*)(orow0 + n) = v;
        }
        if (er0 + 8 < N_EDGES) {
            float2 v = make_float2(acc2[t2][2] + bb0, acc2[t2][3] + bb1);
            *(float2*)(orow0 + (size_t)8 * 128 + n) = v;
        }
    }
}

// ---------------------------------------------------------------------------
extern "C" void kernel_launch(void* const* d_in, const int* in_sizes, int n_in,
                              void* d_out, int out_size) {
    const float* x  = (const float*)d_in[0];
    const int*   ei = (const int*)d_in[1];
    const float* ea = (const float*)d_in[2];
    const float* W1 = (const float*)d_in[3];
    const float* b1 = (const float*)d_in[4];
    const float* W2 = (const float*)d_in[5];
    const float* b2 = (const float*)d_in[6];
    float* out = (float*)d_out;

    cvt_weights_kernel<<<1024, 256>>>(W1, W2);

    cudaFuncSetAttribute(node_pre_kernel, cudaFuncAttributeMaxDynamicSharedMemorySize, P_SMEM);
    dim3 gpre((N_NODES + 127) / 128, 2);
    node_pre_kernel<<<gpre, 256, P_SMEM>>>(x);

    cudaFuncSetAttribute(edge_mma_kernel, cudaFuncAttributeMaxDynamicSharedMemorySize, SMEM_TOTAL);
    int grid = (N_EDGES + 127) / 128;  // 3907
    edge_mma_kernel<<<grid, NTHREADS, SMEM_TOTAL>>>(ei, ea, b1, b2, out);
}

// round 14
// speedup vs baseline: 1.1455x; 1.1455x over previous
#include <cuda_runtime.h>
#include <cuda_fp16.h>
#include <cstdint>

#define N_NODES 50000
#define N_EDGES 500000

// ---------------------------------------------------------------------------
// Transposed f16 weights + precomputed node tables
//   g_W1t[n][k]  n<512, k<384    g_W2t[n][k]  n<128, k<512
//   g_Xs[node][512] = x @ W1[0:128,:]     g_Xt = x @ W1[128:256,:]
// ---------------------------------------------------------------------------
__device__ __half g_W1t[512 * 384];
__device__ __half g_W2t[128 * 512];
__device__ __half g_Xs[(size_t)N_NODES * 512];
__device__ __half g_Xt[(size_t)N_NODES * 512];

__global__ void cvt_weights_kernel(const float* __restrict__ W1,
                                   const float* __restrict__ W2) {
    int idx = blockIdx.x * blockDim.x + threadIdx.x;
    if (idx < 512 * 384) {
        int n = idx / 384, k = idx % 384;
        g_W1t[idx] = __float2half(W1[k * 512 + n]);
    } else if (idx < 512 * 384 + 128 * 512) {
        int j = idx - 512 * 384;
        int n = j / 512, k = j % 512;
        g_W2t[j] = __float2half(W2[k * 128 + n]);
    }
}

// ---------------------------------------------------------------------------
// PTX helpers (baseline features only — plain sm_103 target)
// ---------------------------------------------------------------------------
__device__ __forceinline__ uint32_t s2u(const void* p) {
    uint32_t a;
    asm("{.reg .u64 t; cvta.to.shared.u64 t, %1; cvt.u32.u64 %0, t;}" : "=r"(a) : "l"(p));
    return a;
}
#define CP_ASYNC16(dst, src) \
    asm volatile("cp.async.cg.shared.global [%0], [%1], 16;" :: "r"(dst), "l"(src) : "memory")
#define CP_COMMIT() asm volatile("cp.async.commit_group;" ::: "memory")
#define CP_WAIT(n)  asm volatile("cp.async.wait_group %0;" :: "n"(n) : "memory")

#define LDSM_X4(r0, r1, r2, r3, addr) \
    asm volatile("ldmatrix.sync.aligned.m8n8.x4.shared.b16 {%0,%1,%2,%3}, [%4];" \
                 : "=r"(r0), "=r"(r1), "=r"(r2), "=r"(r3) : "r"(addr))

#define MMA_F16(D, a0, a1, a2, a3, b0, b1) \
    asm volatile("mma.sync.aligned.m16n8k16.row.col.f32.f16.f16.f32 " \
                 "{%0,%1,%2,%3},{%4,%5,%6,%7},{%8,%9},{%0,%1,%2,%3};" \
                 : "+f"((D)[0]), "+f"((D)[1]), "+f"((D)[2]), "+f"((D)[3]) \
                 : "r"(a0), "r"(a1), "r"(a2), "r"(a3), "r"(b0), "r"(b1))

#define STS128(addr, r0, r1, r2, r3) \
    asm volatile("st.shared.v4.b32 [%0], {%1,%2,%3,%4};" \
                 :: "r"(addr), "r"(r0), "r"(r1), "r"(r2), "r"(r3) : "memory")

// A/W1 rows: 128+8 halves = 272 B pitch (conflict-free ldmatrix)
// W2/G rows: 64+8 halves = 144 B pitch
static constexpr uint32_t PITCH_K128 = 272;

// ===========================================================================
// Precompute kernel (unchanged): table = x @ W1slice, f16 out.
// ===========================================================================
static constexpr uint32_t P_OFF_A = 0;
static constexpr uint32_t P_OFF_W = 34816;
static constexpr uint32_t P_WBUF  = 17408;
static constexpr uint32_t P_SMEM  = 69632;

__global__ __launch_bounds__(256, 1) void node_pre_kernel(const float* __restrict__ x) {
    extern __shared__ __align__(1024) char smem[];
    const uint32_t sb = s2u(smem);
    const int tid = threadIdx.x, warp = tid >> 5, lane = tid & 31;
    const int n0 = blockIdx.x * 128;
    const int which = blockIdx.y;
    __half* table = which ? g_Xt : g_Xs;

    auto issue_w = [&](int c, int buf) {
        uint32_t dstb = sb + P_OFF_W + (uint32_t)buf * P_WBUF;
        const __half* src = g_W1t + (size_t)(c * 64) * 384 + which * 128;
#pragma unroll
        for (int i = 0; i < 4; i++) {
            int j = tid + i * 256;
            int rr = j >> 4, q = j & 15;
            CP_ASYNC16(dstb + rr * PITCH_K128 + q * 16, src + rr * 384 + q * 8);
        }
    };
    issue_w(0, 0); CP_COMMIT();

    {
        const int r = tid & 127, hb = tid >> 7;
        const int node = min(n0 + r, N_NODES - 1);
        const float* s = x + (size_t)node * 128 + hb * 64;
#pragma unroll
        for (int j = 0; j < 4; j++) {
            const float4* p = (const float4*)(s + j * 16);
            float4 v0 = p[0], v1 = p[1], v2 = p[2], v3 = p[3];
            __half2 h0 = __floats2half2_rn(v0.x, v0.y), h1 = __floats2half2_rn(v0.z, v0.w);
            __half2 h2 = __floats2half2_rn(v1.x, v1.y), h3 = __floats2half2_rn(v1.z, v1.w);
            __half2 h4 = __floats2half2_rn(v2.x, v2.y), h5 = __floats2half2_rn(v2.z, v2.w);
            __half2 h6 = __floats2half2_rn(v3.x, v3.y), h7 = __floats2half2_rn(v3.z, v3.w);
            uint32_t a = sb + P_OFF_A + r * PITCH_K128 + (hb * 64 + j * 16) * 2;
            STS128(a,      *(uint32_t*)&h0, *(uint32_t*)&h1, *(uint32_t*)&h2, *(uint32_t*)&h3);
            STS128(a + 16, *(uint32_t*)&h4, *(uint32_t*)&h5, *(uint32_t*)&h6, *(uint32_t*)&h7);
        }
    }
    __syncthreads();

    const uint32_t aBase = sb + P_OFF_A + (uint32_t)(warp * 16 + (lane & 15)) * PITCH_K128
                         + ((uint32_t)(lane >> 4) << 4);
    const uint32_t wLane = (uint32_t)(lane & 7) * PITCH_K128 + (((uint32_t)(lane >> 3) & 1) << 4)
                         + (uint32_t)(lane >> 4) * (8 * PITCH_K128);
    const int c2i = (lane & 3) * 2;
    const int r0 = warp * 16 + (lane >> 2);
    const int nd0 = n0 + r0, nd1 = nd0 + 8;

    for (int c = 0; c < 8; c++) {
        CP_WAIT(0);
        __syncthreads();
        if (c < 7) { issue_w(c + 1, (c + 1) & 1); CP_COMMIT(); }

        const uint32_t wb = sb + P_OFF_W + (uint32_t)(c & 1) * P_WBUF + wLane;
        float acc[8][4];
#pragma unroll
        for (int t = 0; t < 8; t++)
#pragma unroll
            for (int j = 0; j < 4; j++) acc[t][j] = 0.f;

#pragma unroll
        for (int s = 0; s < 8; s++) {
            uint32_t a0, a1, a2, a3;
            LDSM_X4(a0, a1, a2, a3, aBase + s * 32);
            uint32_t wrow = wb + s * 32;
#pragma unroll
            for (int tp = 0; tp < 4; tp++) {
                uint32_t b0, b1r, b2r, b3;
                LDSM_X4(b0, b1r, b2r, b3, wrow + tp * (16 * PITCH_K128));
                MMA_F16(acc[2 * tp],     a0, a1, a2, a3, b0,  b1r);
                MMA_F16(acc[2 * tp + 1], a0, a1, a2, a3, b2r, b3);
            }
        }
        __syncthreads();

#pragma unroll
        for (int t = 0; t < 8; t++) {
            int n = c * 64 + t * 8 + c2i;
            if (nd0 < N_NODES) {
                __half2 p = __floats2half2_rn(acc[t][0], acc[t][1]);
                *(__half2*)(table + (size_t)nd0 * 512 + n) = p;
            }
            if (nd1 < N_NODES) {
                __half2 p = __floats2half2_rn(acc[t][2], acc[t][3]);
                *(__half2*)(table + (size_t)nd1 * 512 + n) = p;
            }
        }
    }
}

// ===========================================================================
// Edge kernel: 64 edges/CTA, 128 threads (4 warps), 2 CTAs per SM.
// Same per-warp tiles as the 682us kernel; phase overlap comes from the
// co-resident CTA. W2 single-buffered via split commit groups:
//   top(c): wait(0)+sync; commit {W2[c]}; commit {G[c+1],W1[c+1]}
//   mid(c): wait(1)+sync  (drains W2[c]; leaves next-chunk group in flight)
// ===========================================================================
#define M_EDGES 64
#define NTHREADS 128
static constexpr uint32_t OFF_A   = 0;        // 64 x 272 = 17408
static constexpr uint32_t OFF_W1  = 17408;    // 2 x 17408 = 34816
static constexpr uint32_t W1_BUF  = 17408;
static constexpr uint32_t OFF_W2  = 52224;    // 18432 (single buffer)
static constexpr uint32_t OFF_G   = 70656;    // 2 x 18432 ([2][64] x 144B)
static constexpr uint32_t G_BUF   = 18432;
static constexpr uint32_t G_PITCH = 144;
static constexpr uint32_t OFF_B1  = 107520;   // 512 f32
static constexpr uint32_t OFF_B2  = 109568;   // 128 f32
static constexpr uint32_t OFF_IDX = 110080;   // 128 int
static constexpr uint32_t SMEM_TOTAL = 110592;  // x2 CTAs = 221184 <= 227KB

__global__ __launch_bounds__(NTHREADS, 2) void edge_mma_kernel(
    const int*   __restrict__ edge_index,
    const float* __restrict__ edge_attr,
    const float* __restrict__ b1,
    const float* __restrict__ b2,
    float* __restrict__ out)
{
    extern __shared__ __align__(1024) char smem[];
    const uint32_t sb = s2u(smem);
    const int tid = threadIdx.x, warp = tid >> 5, lane = tid & 31;
    const int e0 = blockIdx.x * M_EDGES;

    float* sB1 = (float*)(smem + OFF_B1);
    float* sB2 = (float*)(smem + OFF_B2);
    int*   sIdx = (int*)(smem + OFF_IDX);   // [0..63]=src, [64..127]=tgt

    auto issue_w1 = [&](int c, int buf) {
        uint32_t dstb = sb + OFF_W1 + (uint32_t)buf * W1_BUF;
        const __half* src = g_W1t + (size_t)(c * 64) * 384 + 256;
#pragma unroll
        for (int i = 0; i < 8; i++) {           // 64 rows x 16 segs = 1024
            int j = tid + i * NTHREADS;
            int rr = j >> 4, q = j & 15;
            CP_ASYNC16(dstb + rr * PITCH_K128 + q * 16, src + rr * 384 + q * 8);
        }
    };
    auto issue_w2 = [&](int c) {
        uint32_t dstb = sb + OFF_W2;
        const __half* src = g_W2t + c * 64;
#pragma unroll
        for (int i = 0; i < 8; i++) {           // 128 rows x 8 segs = 1024
            int j = tid + i * NTHREADS;
            int rr = j >> 3, q = j & 7;
            CP_ASYNC16(dstb + rr * 144 + q * 16, src + (size_t)rr * 512 + q * 8);
        }
    };
    auto issue_g = [&](int c, int buf) {
        uint32_t dstb = sb + OFF_G + (uint32_t)buf * G_BUF;
        const int cc = c * 64;
#pragma unroll
        for (int i = 0; i < 8; i++) {           // 2 tables x 64 edges x 8 segs = 1024
            int j = tid + i * NTHREADS;
            int seg = j & 7, rest = j >> 3;     // rest 0..127
            int tbl = rest >> 6;
            int row = sIdx[rest];
            const __half* src = (tbl ? g_Xt : g_Xs) + (size_t)row * 512 + cc + seg * 8;
            CP_ASYNC16(dstb + (uint32_t)rest * G_PITCH + seg * 16, src);
        }
    };

    // ---- prologue ----
    {
        int half = tid >> 6, r = tid & 63;
        int e = min(e0 + r, N_EDGES - 1);
        sIdx[tid] = edge_index[(size_t)half * N_EDGES + e];
    }
    for (int i = tid; i < 512; i += NTHREADS) sB1[i] = b1[i];
    for (int i = tid; i < 128; i += NTHREADS) sB2[i] = b2[i];

    {   // A build: 2 threads per row, 64 cols each
        const int r = tid >> 1, hb = tid & 1;
        const int e = min(e0 + r, N_EDGES - 1);
        const float* s = edge_attr + (size_t)e * 128 + hb * 64;
#pragma unroll
        for (int j = 0; j < 4; j++) {
            const float4* p = (const float4*)(s + j * 16);
            float4 v0 = p[0], v1 = p[1], v2 = p[2], v3 = p[3];
            __half2 h0 = __floats2half2_rn(v0.x, v0.y), h1 = __floats2half2_rn(v0.z, v0.w);
            __half2 h2 = __floats2half2_rn(v1.x, v1.y), h3 = __floats2half2_rn(v1.z, v1.w);
            __half2 h4 = __floats2half2_rn(v2.x, v2.y), h5 = __floats2half2_rn(v2.z, v2.w);
            __half2 h6 = __floats2half2_rn(v3.x, v3.y), h7 = __floats2half2_rn(v3.z, v3.w);
            uint32_t a = sb + OFF_A + r * PITCH_K128 + (hb * 64 + j * 16) * 2;
            STS128(a,      *(uint32_t*)&h0, *(uint32_t*)&h1, *(uint32_t*)&h2, *(uint32_t*)&h3);
            STS128(a + 16, *(uint32_t*)&h4, *(uint32_t*)&h5, *(uint32_t*)&h6, *(uint32_t*)&h7);
        }
    }
    __syncthreads();        // sIdx visible before gather issue

    issue_g(0, 0); issue_w1(0, 0); CP_COMMIT();   // group A_0

    // ---- per-thread fragment addresses ----
    const uint32_t aBase = sb + OFF_A + (uint32_t)(warp * 16 + (lane & 15)) * PITCH_K128
                         + ((uint32_t)(lane >> 4) << 4);
    const uint32_t wLane1 = (uint32_t)(lane & 7) * PITCH_K128 + (((uint32_t)(lane >> 3) & 1) << 4)
                          + (uint32_t)(lane >> 4) * (8 * PITCH_K128);
    const uint32_t wLane2 = (uint32_t)(lane & 7) * 144 + (((uint32_t)(lane >> 3) & 1) << 4)
                          + (uint32_t)(lane >> 4) * 1152;
    const int c2i = (lane & 3) * 2;
    const int r0 = warp * 16 + (lane >> 2);        // local edge row 0..63
    const uint32_t gRd = (uint32_t)r0 * G_PITCH + (uint32_t)c2i * 2;

    float acc2[16][4];
#pragma unroll
    for (int t = 0; t < 16; t++)
#pragma unroll
        for (int j = 0; j < 4; j++) acc2[t][j] = 0.f;

    for (int c = 0; c < 8; c++) {
        CP_WAIT(0);                 // G[c], W1[c] resident
        __syncthreads();            // everyone past layer2(c-1): W2 buf free
        issue_w2(c); CP_COMMIT();                      // group B_c
        if (c < 7) { issue_g(c + 1, (c + 1) & 1);
                     issue_w1(c + 1, (c + 1) & 1); CP_COMMIT(); }  // group A_{c+1}

        // ----- layer 1: A[64x128] @ W1c_chunk[128x64] -----
        const uint32_t wb = sb + OFF_W1 + (uint32_t)(c & 1) * W1_BUF + wLane1;
        float acc1[8][4];
#pragma unroll
        for (int t = 0; t < 8; t++)
#pragma unroll
            for (int j = 0; j < 4; j++) acc1[t][j] = 0.f;

#pragma unroll
        for (int s = 0; s < 8; s++) {
            uint32_t a0, a1, a2, a3;
            LDSM_X4(a0, a1, a2, a3, aBase + s * 32);
            uint32_t wrow = wb + s * 32;
#pragma unroll
            for (int tp = 0; tp < 4; tp++) {
                uint32_t b0, b1r, b2r, b3;
                LDSM_X4(b0, b1r, b2r, b3, wrow + tp * (16 * PITCH_K128));
                MMA_F16(acc1[2 * tp],     a0, a1, a2, a3, b0,  b1r);
                MMA_F16(acc1[2 * tp + 1], a0, a1, a2, a3, b2r, b3);
            }
        }

        // ----- epilogue: + Xs + Xt + b1 (smem stage), ReLU, pack A2-frags -----
        const uint32_t gb = sb + OFF_G + (uint32_t)(c & 1) * G_BUF + gRd;
        uint32_t hfrag[4][4];
#pragma unroll
        for (int tp = 0; tp < 4; tp++) {
#pragma unroll
            for (int hh = 0; hh < 2; hh++) {
                int t = 2 * tp + hh;
                uint32_t off = (uint32_t)t * 16;
                uint32_t us0, ut0, us1, ut1;
                asm volatile("ld.shared.b32 %0, [%1];" : "=r"(us0) : "r"(gb + off));
                asm volatile("ld.shared.b32 %0, [%1];" : "=r"(ut0) : "r"(gb + 64 * G_PITCH + off));
                asm volatile("ld.shared.b32 %0, [%1];" : "=r"(us1) : "r"(gb + 8 * G_PITCH + off));
                asm volatile("ld.shared.b32 %0, [%1];" : "=r"(ut1) : "r"(gb + 72 * G_PITCH + off));
                int n = c * 64 + t * 8 + c2i;
                float bb0 = sB1[n], bb1 = sB1[n + 1];
                float2 s0 = __half22float2(*(__half2*)&us0);
                float2 t0 = __half22float2(*(__half2*)&ut0);
                float2 s1 = __half22float2(*(__half2*)&us1);
                float2 t1 = __half22float2(*(__half2*)&ut1);
                float v0 = fmaxf(acc1[t][0] + s0.x + t0.x + bb0, 0.f);
                float v1 = fmaxf(acc1[t][1] + s0.y + t0.y + bb1, 0.f);
                float v2 = fmaxf(acc1[t][2] + s1.x + t1.x + bb0, 0.f);
                float v3 = fmaxf(acc1[t][3] + s1.y + t1.y + bb1, 0.f);
                __half2 p0 = __floats2half2_rn(v0, v1);
                __half2 p1 = __floats2half2_rn(v2, v3);
                hfrag[tp][2 * hh]     = *(uint32_t*)&p0;
                hfrag[tp][2 * hh + 1] = *(uint32_t*)&p1;
            }
        }

        // ----- wait W2[c] (oldest outstanding), leave A_{c+1} flying -----
        if (c < 7) { CP_WAIT(1); } else { CP_WAIT(0); }
        __syncthreads();

        // ----- layer 2: out += Hchunk[64x64] @ W2chunk[64x128] -----
        const uint32_t w2b = sb + OFF_W2 + wLane2;
#pragma unroll
        for (int s2 = 0; s2 < 4; s2++) {
            uint32_t ha0 = hfrag[s2][0], ha1 = hfrag[s2][1];
            uint32_t ha2 = hfrag[s2][2], ha3 = hfrag[s2][3];
#pragma unroll
            for (int t2p = 0; t2p < 8; t2p++) {
                uint32_t b0, b1r, b2r, b3;
                LDSM_X4(b0, b1r, b2r, b3, w2b + s2 * 32 + t2p * 2304);
                MMA_F16(acc2[2 * t2p],     ha0, ha1, ha2, ha3, b0,  b1r);
                MMA_F16(acc2[2 * t2p + 1], ha0, ha1, ha2, ha3, b2r, b3);
            }
        }
    }

    // ---- output: + b2 ----
    const int er0 = e0 + r0;
    float* orow0 = out + (size_t)er0 * 128;
#pragma unroll
    for (int t2 = 0; t2 < 16; t2++) {
        int n = t2 * 8 + c2i;
        float bb0 = sB2[n], bb1 = sB2[n + 1];
        if (er0 < N_EDGES) {
            float2 v = make_float2(acc2[t2][0] + bb0, acc2[t2][1] + bb1);
            *(float2*)(orow0 + n) = v;
        }
        if (er0 + 8 < N_EDGES) {
            float2 v = make_float2(acc2[t2][2] + bb0, acc2[t2][3] + bb1);
            *(float2*)(orow0 + (size_t)8 * 128 + n) = v;
        }
    }
}

// ---------------------------------------------------------------------------
extern "C" void kernel_launch(void* const* d_in, const int* in_sizes, int n_in,
                              void* d_out, int out_size) {
    const float* x  = (const float*)d_in[0];
    const int*   ei = (const int*)d_in[1];
    const float* ea = (const float*)d_in[2];
    const float* W1 = (const float*)d_in[3];
    const float* b1 = (const float*)d_in[4];
    const float* W2 = (const float*)d_in[5];
    const float* b2 = (const float*)d_in[6];
    float* out = (float*)d_out;

    cvt_weights_kernel<<<1024, 256>>>(W1, W2);

    cudaFuncSetAttribute(node_pre_kernel, cudaFuncAttributeMaxDynamicSharedMemorySize, P_SMEM);
    dim3 gpre((N_NODES + 127) / 128, 2);
    node_pre_kernel<<<gpre, 256, P_SMEM>>>(x);

    cudaFuncSetAttribute(edge_mma_kernel, cudaFuncAttributeMaxDynamicSharedMemorySize, SMEM_TOTAL);
    int grid = (N_EDGES + M_EDGES - 1) / M_EDGES;  // 7813
    edge_mma_kernel<<<grid, NTHREADS, SMEM_TOTAL>>>(ei, ea, b1, b2, out);
}

// round 15
// speedup vs baseline: 1.2076x; 1.0542x over previous
#include <cuda_runtime.h>
#include <cuda_fp16.h>
#include <cstdint>

#define N_NODES 50000
#define N_EDGES 500000

// ---------------------------------------------------------------------------
// Transposed f16 weights + precomputed node tables
//   g_W1t[n][k]  n<512, k<384    g_W2t[n][k]  n<128, k<512
//   g_Xs[node][512] = x @ W1[0:128,:]     g_Xt = x @ W1[128:256,:]
// ---------------------------------------------------------------------------
__device__ __half g_W1t[512 * 384];
__device__ __half g_W2t[128 * 512];
__device__ __half g_Xs[(size_t)N_NODES * 512];
__device__ __half g_Xt[(size_t)N_NODES * 512];

__global__ void cvt_weights_kernel(const float* __restrict__ W1,
                                   const float* __restrict__ W2) {
    int idx = blockIdx.x * blockDim.x + threadIdx.x;
    if (idx < 512 * 384) {
        int n = idx / 384, k = idx % 384;
        g_W1t[idx] = __float2half(W1[k * 512 + n]);
    } else if (idx < 512 * 384 + 128 * 512) {
        int j = idx - 512 * 384;
        int n = j / 512, k = j % 512;
        g_W2t[j] = __float2half(W2[k * 128 + n]);
    }
}

// ---------------------------------------------------------------------------
// PTX helpers (baseline features only — plain sm_103 target)
// ---------------------------------------------------------------------------
__device__ __forceinline__ uint32_t s2u(const void* p) {
    uint32_t a;
    asm("{.reg .u64 t; cvta.to.shared.u64 t, %1; cvt.u32.u64 %0, t;}" : "=r"(a) : "l"(p));
    return a;
}
#define CP_ASYNC16(dst, src) \
    asm volatile("cp.async.cg.shared.global [%0], [%1], 16;" :: "r"(dst), "l"(src) : "memory")
#define CP_COMMIT() asm volatile("cp.async.commit_group;" ::: "memory")
#define CP_WAIT(n)  asm volatile("cp.async.wait_group %0;" :: "n"(n) : "memory")

#define LDSM_X4(r0, r1, r2, r3, addr) \
    asm volatile("ldmatrix.sync.aligned.m8n8.x4.shared.b16 {%0,%1,%2,%3}, [%4];" \
                 : "=r"(r0), "=r"(r1), "=r"(r2), "=r"(r3) : "r"(addr))

#define MMA_F16(D, a0, a1, a2, a3, b0, b1) \
    asm volatile("mma.sync.aligned.m16n8k16.row.col.f32.f16.f16.f32 " \
                 "{%0,%1,%2,%3},{%4,%5,%6,%7},{%8,%9},{%0,%1,%2,%3};" \
                 : "+f"((D)[0]), "+f"((D)[1]), "+f"((D)[2]), "+f"((D)[3]) \
                 : "r"(a0), "r"(a1), "r"(a2), "r"(a3), "r"(b0), "r"(b1))

#define STS128(addr, r0, r1, r2, r3) \
    asm volatile("st.shared.v4.b32 [%0], {%1,%2,%3,%4};" \
                 :: "r"(addr), "r"(r0), "r"(r1), "r"(r2), "r"(r3) : "memory")

// A/W1 rows: 128+8 halves = 272 B pitch (conflict-free ldmatrix)
// W2/G rows: 64+8 halves = 144 B pitch
static constexpr uint32_t PITCH_K128 = 272;

// ===========================================================================
// Precompute kernel (unchanged): table = x @ W1slice, f16 out.
// ===========================================================================
static constexpr uint32_t P_OFF_A = 0;
static constexpr uint32_t P_OFF_W = 34816;
static constexpr uint32_t P_WBUF  = 17408;
static constexpr uint32_t P_SMEM  = 69632;

__global__ __launch_bounds__(256, 1) void node_pre_kernel(const float* __restrict__ x) {
    extern __shared__ __align__(1024) char smem[];
    const uint32_t sb = s2u(smem);
    const int tid = threadIdx.x, warp = tid >> 5, lane = tid & 31;
    const int n0 = blockIdx.x * 128;
    const int which = blockIdx.y;
    __half* table = which ? g_Xt : g_Xs;

    auto issue_w = [&](int c, int buf) {
        uint32_t dstb = sb + P_OFF_W + (uint32_t)buf * P_WBUF;
        const __half* src = g_W1t + (size_t)(c * 64) * 384 + which * 128;
#pragma unroll
        for (int i = 0; i < 4; i++) {
            int j = tid + i * 256;
            int rr = j >> 4, q = j & 15;
            CP_ASYNC16(dstb + rr * PITCH_K128 + q * 16, src + rr * 384 + q * 8);
        }
    };
    issue_w(0, 0); CP_COMMIT();

    {
        const int r = tid & 127, hb = tid >> 7;
        const int node = min(n0 + r, N_NODES - 1);
        const float* s = x + (size_t)node * 128 + hb * 64;
#pragma unroll
        for (int j = 0; j < 4; j++) {
            const float4* p = (const float4*)(s + j * 16);
            float4 v0 = p[0], v1 = p[1], v2 = p[2], v3 = p[3];
            __half2 h0 = __floats2half2_rn(v0.x, v0.y), h1 = __floats2half2_rn(v0.z, v0.w);
            __half2 h2 = __floats2half2_rn(v1.x, v1.y), h3 = __floats2half2_rn(v1.z, v1.w);
            __half2 h4 = __floats2half2_rn(v2.x, v2.y), h5 = __floats2half2_rn(v2.z, v2.w);
            __half2 h6 = __floats2half2_rn(v3.x, v3.y), h7 = __floats2half2_rn(v3.z, v3.w);
            uint32_t a = sb + P_OFF_A + r * PITCH_K128 + (hb * 64 + j * 16) * 2;
            STS128(a,      *(uint32_t*)&h0, *(uint32_t*)&h1, *(uint32_t*)&h2, *(uint32_t*)&h3);
            STS128(a + 16, *(uint32_t*)&h4, *(uint32_t*)&h5, *(uint32_t*)&h6, *(uint32_t*)&h7);
        }
    }
    __syncthreads();

    const uint32_t aBase = sb + P_OFF_A + (uint32_t)(warp * 16 + (lane & 15)) * PITCH_K128
                         + ((uint32_t)(lane >> 4) << 4);
    const uint32_t wLane = (uint32_t)(lane & 7) * PITCH_K128 + (((uint32_t)(lane >> 3) & 1) << 4)
                         + (uint32_t)(lane >> 4) * (8 * PITCH_K128);
    const int c2i = (lane & 3) * 2;
    const int r0 = warp * 16 + (lane >> 2);
    const int nd0 = n0 + r0, nd1 = nd0 + 8;

    for (int c = 0; c < 8; c++) {
        CP_WAIT(0);
        __syncthreads();
        if (c < 7) { issue_w(c + 1, (c + 1) & 1); CP_COMMIT(); }

        const uint32_t wb = sb + P_OFF_W + (uint32_t)(c & 1) * P_WBUF + wLane;
        float acc[8][4];
#pragma unroll
        for (int t = 0; t < 8; t++)
#pragma unroll
            for (int j = 0; j < 4; j++) acc[t][j] = 0.f;

#pragma unroll
        for (int s = 0; s < 8; s++) {
            uint32_t a0, a1, a2, a3;
            LDSM_X4(a0, a1, a2, a3, aBase + s * 32);
            uint32_t wrow = wb + s * 32;
#pragma unroll
            for (int tp = 0; tp < 4; tp++) {
                uint32_t b0, b1r, b2r, b3;
                LDSM_X4(b0, b1r, b2r, b3, wrow + tp * (16 * PITCH_K128));
                MMA_F16(acc[2 * tp],     a0, a1, a2, a3, b0,  b1r);
                MMA_F16(acc[2 * tp + 1], a0, a1, a2, a3, b2r, b3);
            }
        }
        __syncthreads();

#pragma unroll
        for (int t = 0; t < 8; t++) {
            int n = c * 64 + t * 8 + c2i;
            if (nd0 < N_NODES) {
                __half2 p = __floats2half2_rn(acc[t][0], acc[t][1]);
                *(__half2*)(table + (size_t)nd0 * 512 + n) = p;
            }
            if (nd1 < N_NODES) {
                __half2 p = __floats2half2_rn(acc[t][2], acc[t][3]);
                *(__half2*)(table + (size_t)nd1 * 512 + n) = p;
            }
        }
    }
}

// ===========================================================================
// Edge kernel (R11 config + A-fragment register hoisting):
// 128 edges/CTA, 256 threads, occ 1. layer1 = ea @ W1c (K=128) + gathers,
// ReLU; layer2 = H @ W2. A fragments are identical across the 8 N-chunks,
// so they are ldmatrix'ed ONCE into registers before the chunk loop.
// ===========================================================================
static constexpr uint32_t OFF_A   = 0;        // 128 x 272 = 34816
static constexpr uint32_t OFF_W1  = 34816;    // 2 x 17408 = 34816
static constexpr uint32_t W1_BUF  = 17408;
static constexpr uint32_t OFF_W2  = 69632;    // 2 x 18432 = 36864
static constexpr uint32_t W2_BUF  = 18432;
static constexpr uint32_t OFF_G   = 106496;   // 2 x 36864 = 73728 ([2][128] x 144B)
static constexpr uint32_t G_BUF   = 36864;
static constexpr uint32_t G_PITCH = 144;
static constexpr uint32_t OFF_B1  = 180224;   // 512 f32
static constexpr uint32_t OFF_B2  = 182272;   // 128 f32
static constexpr uint32_t OFF_IDX = 182784;   // 256 int
static constexpr uint32_t SMEM_TOTAL = 183808;

__global__ __launch_bounds__(256, 1) void edge_mma_kernel(
    const int*   __restrict__ edge_index,
    const float* __restrict__ edge_attr,
    const float* __restrict__ b1,
    const float* __restrict__ b2,
    float* __restrict__ out)
{
    extern __shared__ __align__(1024) char smem[];
    const uint32_t sb = s2u(smem);
    const int tid = threadIdx.x, warp = tid >> 5, lane = tid & 31;
    const int e0 = blockIdx.x * 128;

    float* sB1 = (float*)(smem + OFF_B1);
    float* sB2 = (float*)(smem + OFF_B2);
    int*   sIdx = (int*)(smem + OFF_IDX);   // [0..127]=src, [128..255]=tgt

    auto issue_w1 = [&](int c, int buf) {
        uint32_t dstb = sb + OFF_W1 + (uint32_t)buf * W1_BUF;
        const __half* src = g_W1t + (size_t)(c * 64) * 384 + 256;
#pragma unroll
        for (int i = 0; i < 4; i++) {           // 64 rows x 16 segs = 1024
            int j = tid + i * 256;
            int rr = j >> 4, q = j & 15;
            CP_ASYNC16(dstb + rr * PITCH_K128 + q * 16, src + rr * 384 + q * 8);
        }
    };
    auto issue_w2 = [&](int c, int buf) {
        uint32_t dstb = sb + OFF_W2 + (uint32_t)buf * W2_BUF;
        const __half* src = g_W2t + c * 64;
#pragma unroll
        for (int i = 0; i < 4; i++) {           // 128 rows x 8 segs = 1024
            int j = tid + i * 256;
            int rr = j >> 3, q = j & 7;
            CP_ASYNC16(dstb + rr * 144 + q * 16, src + (size_t)rr * 512 + q * 8);
        }
    };
    auto issue_g = [&](int c, int buf) {
        uint32_t dstb = sb + OFF_G + (uint32_t)buf * G_BUF;
        const int cc = c * 64;
#pragma unroll
        for (int i = 0; i < 8; i++) {           // 2 tables x 128 edges x 8 segs = 2048
            int j = tid + i * 256;
            int seg = j & 7, rest = j >> 3;     // rest 0..255
            int row = sIdx[rest];
            const __half* src = ((rest >> 7) ? g_Xt : g_Xs) + (size_t)row * 512 + cc + seg * 8;
            CP_ASYNC16(dstb + (uint32_t)rest * G_PITCH + seg * 16, src);
        }
    };

    // ---- prologue: indices, biases, A tile, then sync, then prefetch ----
    if (tid < 256) {
        int half = tid >> 7, r = tid & 127;
        int e = min(e0 + r, N_EDGES - 1);
        sIdx[tid] = edge_index[(size_t)half * N_EDGES + e];
    }
    for (int i = tid; i < 512; i += 256) sB1[i] = b1[i];
    for (int i = tid; i < 128; i += 256) sB2[i] = b2[i];

    {   // A build: edge_attr rows -> f16 smem (2 threads per row)
        const int r = tid & 127, hb = tid >> 7;
        const int e = min(e0 + r, N_EDGES - 1);
        const float* s = edge_attr + (size_t)e * 128 + hb * 64;
#pragma unroll
        for (int j = 0; j < 4; j++) {
            const float4* p = (const float4*)(s + j * 16);
            float4 v0 = p[0], v1 = p[1], v2 = p[2], v3 = p[3];
            __half2 h0 = __floats2half2_rn(v0.x, v0.y), h1 = __floats2half2_rn(v0.z, v0.w);
            __half2 h2 = __floats2half2_rn(v1.x, v1.y), h3 = __floats2half2_rn(v1.z, v1.w);
            __half2 h4 = __floats2half2_rn(v2.x, v2.y), h5 = __floats2half2_rn(v2.z, v2.w);
            __half2 h6 = __floats2half2_rn(v3.x, v3.y), h7 = __floats2half2_rn(v3.z, v3.w);
            uint32_t a = sb + OFF_A + r * PITCH_K128 + (hb * 64 + j * 16) * 2;
            STS128(a,      *(uint32_t*)&h0, *(uint32_t*)&h1, *(uint32_t*)&h2, *(uint32_t*)&h3);
            STS128(a + 16, *(uint32_t*)&h4, *(uint32_t*)&h5, *(uint32_t*)&h6, *(uint32_t*)&h7);
        }
    }
    __syncthreads();        // sIdx + A visible

    issue_g(0, 0); issue_w1(0, 0); issue_w2(0, 0); CP_COMMIT();

    // ---- per-thread fragment addresses ----
    const uint32_t aBase = sb + OFF_A + (uint32_t)(warp * 16 + (lane & 15)) * PITCH_K128
                         + ((uint32_t)(lane >> 4) << 4);
    const uint32_t wLane1 = (uint32_t)(lane & 7) * PITCH_K128 + (((uint32_t)(lane >> 3) & 1) << 4)
                          + (uint32_t)(lane >> 4) * (8 * PITCH_K128);
    const uint32_t wLane2 = (uint32_t)(lane & 7) * 144 + (((uint32_t)(lane >> 3) & 1) << 4)
                          + (uint32_t)(lane >> 4) * 1152;
    const int c2i = (lane & 3) * 2;
    const int r0 = warp * 16 + (lane >> 2);        // local edge row (0..127)
    const uint32_t gRd = (uint32_t)r0 * G_PITCH + (uint32_t)c2i * 2;

    // ---- hoist A fragments: same for every chunk (K=128 fixed) ----
    uint32_t aF[8][4];
#pragma unroll
    for (int s = 0; s < 8; s++)
        LDSM_X4(aF[s][0], aF[s][1], aF[s][2], aF[s][3], aBase + s * 32);

    float acc2[16][4];
#pragma unroll
    for (int t = 0; t < 16; t++)
#pragma unroll
        for (int j = 0; j < 4; j++) acc2[t][j] = 0.f;

    for (int c = 0; c < 8; c++) {
        CP_WAIT(0);                 // chunk c data resident
        __syncthreads();            // all warps done with chunk c-1 buffers
        if (c < 7) {
            issue_g(c + 1, (c + 1) & 1);
            issue_w1(c + 1, (c + 1) & 1);
            issue_w2(c + 1, (c + 1) & 1);
            CP_COMMIT();
        }

        // ----- layer 1: A-frags (regs) @ W1c_chunk[128x64] -----
        const uint32_t wb = sb + OFF_W1 + (uint32_t)(c & 1) * W1_BUF + wLane1;
        float acc1[8][4];
#pragma unroll
        for (int t = 0; t < 8; t++)
#pragma unroll
            for (int j = 0; j < 4; j++) acc1[t][j] = 0.f;

#pragma unroll
        for (int s = 0; s < 8; s++) {
            uint32_t wrow = wb + s * 32;
#pragma unroll
            for (int tp = 0; tp < 4; tp++) {
                uint32_t b0, b1r, b2r, b3;
                LDSM_X4(b0, b1r, b2r, b3, wrow + tp * (16 * PITCH_K128));
                MMA_F16(acc1[2 * tp],     aF[s][0], aF[s][1], aF[s][2], aF[s][3], b0,  b1r);
                MMA_F16(acc1[2 * tp + 1], aF[s][0], aF[s][1], aF[s][2], aF[s][3], b2r, b3);
            }
        }

        // ----- epilogue: + Xs + Xt + b1 (smem stage), ReLU, pack A2-frags -----
        const uint32_t gb = sb + OFF_G + (uint32_t)(c & 1) * G_BUF + gRd;
        uint32_t hfrag[4][4];
#pragma unroll
        for (int tp = 0; tp < 4; tp++) {
#pragma unroll
            for (int hh = 0; hh < 2; hh++) {
                int t = 2 * tp + hh;
                uint32_t off = (uint32_t)t * 16;
                uint32_t us0, ut0, us1, ut1;
                asm volatile("ld.shared.b32 %0, [%1];" : "=r"(us0) : "r"(gb + off));
                asm volatile("ld.shared.b32 %0, [%1];" : "=r"(ut0) : "r"(gb + 128 * G_PITCH + off));
                asm volatile("ld.shared.b32 %0, [%1];" : "=r"(us1) : "r"(gb + 8 * G_PITCH + off));
                asm volatile("ld.shared.b32 %0, [%1];" : "=r"(ut1) : "r"(gb + 136 * G_PITCH + off));
                int n = c * 64 + t * 8 + c2i;
                float bb0 = sB1[n], bb1 = sB1[n + 1];
                float2 s0 = __half22float2(*(__half2*)&us0);
                float2 t0 = __half22float2(*(__half2*)&ut0);
                float2 s1 = __half22float2(*(__half2*)&us1);
                float2 t1 = __half22float2(*(__half2*)&ut1);
                float v0 = fmaxf(acc1[t][0] + s0.x + t0.x + bb0, 0.f);
                float v1 = fmaxf(acc1[t][1] + s0.y + t0.y + bb1, 0.f);
                float v2 = fmaxf(acc1[t][2] + s1.x + t1.x + bb0, 0.f);
                float v3 = fmaxf(acc1[t][3] + s1.y + t1.y + bb1, 0.f);
                __half2 p0 = __floats2half2_rn(v0, v1);
                __half2 p1 = __floats2half2_rn(v2, v3);
                hfrag[tp][2 * hh]     = *(uint32_t*)&p0;
                hfrag[tp][2 * hh + 1] = *(uint32_t*)&p1;
            }
        }

        // ----- layer 2: out += Hchunk[128x64] @ W2chunk[64x128] -----
        const uint32_t w2b = sb + OFF_W2 + (uint32_t)(c & 1) * W2_BUF + wLane2;
#pragma unroll
        for (int s2 = 0; s2 < 4; s2++) {
            uint32_t ha0 = hfrag[s2][0], ha1 = hfrag[s2][1];
            uint32_t ha2 = hfrag[s2][2], ha3 = hfrag[s2][3];
#pragma unroll
            for (int t2p = 0; t2p < 8; t2p++) {
                uint32_t b0, b1r, b2r, b3;
                LDSM_X4(b0, b1r, b2r, b3, w2b + s2 * 32 + t2p * 2304);
                MMA_F16(acc2[2 * t2p],     ha0, ha1, ha2, ha3, b0,  b1r);
                MMA_F16(acc2[2 * t2p + 1], ha0, ha1, ha2, ha3, b2r, b3);
            }
        }
    }

    // ---- output: + b2 ----
    const int er0 = e0 + r0;
    float* orow0 = out + (size_t)er0 * 128;
#pragma unroll
    for (int t2 = 0; t2 < 16; t2++) {
        int n = t2 * 8 + c2i;
        float bb0 = sB2[n], bb1 = sB2[n + 1];
        if (er0 < N_EDGES) {
            float2 v = make_float2(acc2[t2][0] + bb0, acc2[t2][1] + bb1);
            *(float2*)(orow0 + n) = v;
        }
        if (er0 + 8 < N_EDGES) {
            float2 v = make_float2(acc2[t2][2] + bb0, acc2[t2][3] + bb1);
            *(float2*)(orow0 + (size_t)8 * 128 + n) = v;
        }
    }
}

// ---------------------------------------------------------------------------
extern "C" void kernel_launch(void* const* d_in, const int* in_sizes, int n_in,
                              void* d_out, int out_size) {
    const float* x  = (const float*)d_in[0];
    const int*   ei = (const int*)d_in[1];
    const float* ea = (const float*)d_in[2];
    const float* W1 = (const float*)d_in[3];
    const float* b1 = (const float*)d_in[4];
    const float* W2 = (const float*)d_in[5];
    const float* b2 = (const float*)d_in[6];
    float* out = (float*)d_out;

    cvt_weights_kernel<<<1024, 256>>>(W1, W2);

    cudaFuncSetAttribute(node_pre_kernel, cudaFuncAttributeMaxDynamicSharedMemorySize, P_SMEM);
    dim3 gpre((N_NODES + 127) / 128, 2);
    node_pre_kernel<<<gpre, 256, P_SMEM>>>(x);

    cudaFuncSetAttribute(edge_mma_kernel, cudaFuncAttributeMaxDynamicSharedMemorySize, SMEM_TOTAL);
    int grid = (N_EDGES + 127) / 128;  // 3907
    edge_mma_kernel<<<grid, 256, SMEM_TOTAL>>>(ei, ea, b1, b2, out);
}